// round 11
// baseline (speedup 1.0000x reference)
#include <cuda_runtime.h>
#include <mma.h>
#include <cuda_fp16.h>
#include <cstdint>

using namespace nvcuda;

// Problem constants
static constexpr int B_ = 2;
static constexpr int C_ = 4;
static constexpr int T_ = 512;
static constexpr int K_ = 1024;
static constexpr int E_ = 1024;
static constexpr int H_ = 16;
static constexpr int D_ = 64;

// Scratch (device globals, allocation-free). All GEMM operands in fp16.
__device__ __half h_HS[B_ * T_ * E_];       //  2 MB
__device__ __half h_KV[B_ * C_ * K_ * E_];  // 16 MB
__device__ __half h_Wq[E_ * E_];
__device__ __half h_Wk[E_ * E_];
__device__ __half h_Wv[E_ * E_];
__device__ __half h_Wo[E_ * E_];
__device__ __half h_Q[B_ * T_ * E_];        //  2 MB
__device__ __half h_K[B_ * C_ * K_ * E_];   // 16 MB
__device__ __half h_V[B_ * C_ * K_ * E_];   // 16 MB
__device__ __half h_attn[B_ * T_ * E_];     //  2 MB

// ---------------------------------------------------------------------------
// Helpers
// ---------------------------------------------------------------------------
__device__ __forceinline__ uint32_t smem_u32(const void* p) {
    uint32_t a;
    asm("{ .reg .u64 t; cvta.to.shared.u64 t, %1; cvt.u32.u64 %0, t; }"
        : "=r"(a) : "l"(p));
    return a;
}

__device__ __forceinline__ void cp16(uint32_t saddr, const void* g) {
    asm volatile("cp.async.cg.shared.global [%0], [%1], 16;"
                 :: "r"(saddr), "l"(g) : "memory");
}
#define CP_COMMIT() asm volatile("cp.async.commit_group;" ::: "memory")
#define CP_WAIT0()  asm volatile("cp.async.wait_group 0;" ::: "memory")
#define CP_WAIT1()  asm volatile("cp.async.wait_group 1;" ::: "memory")

// ---------------------------------------------------------------------------
// Fused float -> fp16 (RN) conversion for all six operand tensors, one launch.
// ---------------------------------------------------------------------------
static constexpr int N4_HS = (B_ * T_ * E_) / 4;          // 262144
static constexpr int N4_KV = (B_ * C_ * K_ * E_) / 4;     // 2097152
static constexpr int N4_W  = (E_ * E_) / 4;               // 262144
static constexpr int N4_TOTAL = N4_HS + N4_KV + 4 * N4_W; // 3407872

__global__ void f2h_all(const float4* __restrict__ hs,
                        const float4* __restrict__ kvs,
                        const float4* __restrict__ wq, const float4* __restrict__ wk,
                        const float4* __restrict__ wv, const float4* __restrict__ wo,
                        uint2* __restrict__ ohs, uint2* __restrict__ okv,
                        uint2* __restrict__ owq, uint2* __restrict__ owk,
                        uint2* __restrict__ owv, uint2* __restrict__ owo)
{
    int i = blockIdx.x * 256 + threadIdx.x;
    if (i >= N4_TOTAL) return;
    const float4* src;
    uint2* dst;
    int j = i;
    if (j < N4_HS)                 { src = hs;  dst = ohs; }
    else if ((j -= N4_HS) < N4_KV) { src = kvs; dst = okv; }
    else if ((j -= N4_KV) < N4_W)  { src = wq;  dst = owq; }
    else if ((j -= N4_W) < N4_W)   { src = wk;  dst = owk; }
    else if ((j -= N4_W) < N4_W)   { src = wv;  dst = owv; }
    else { j -= N4_W;                src = wo;  dst = owo; }
    float4 v = src[j];
    __half2 a = __floats2half2_rn(v.x, v.y);
    __half2 b = __floats2half2_rn(v.z, v.w);
    dst[j] = make_uint2(*(uint32_t*)&a, *(uint32_t*)&b);
}

// ---------------------------------------------------------------------------
// fp16 wmma projection GEMM (128x128 tile — Q and O projections):
// identical to R10 proven version.
// ---------------------------------------------------------------------------
static constexpr int SLDH = 72;
static constexpr int SMEM_PROJ = 3 * 256 * SLDH * 2;   // 110592 B

__global__ __launch_bounds__(256, 2) void proj_kernel(
    const __half* __restrict__ A,
    const __half* __restrict__ Bw,
    const float* __restrict__ bias,
    __half* __restrict__ Ch, float* __restrict__ Cf,
    float scale)
{
    extern __shared__ __half smh[];
    const uint32_t sbase = smem_u32(smh);

    const int m0 = blockIdx.y * 128;
    const int n0 = blockIdx.x * 128;

    const int tid  = threadIdx.x;
    const int w    = tid >> 5;
    const int lane = tid & 31;
    const int wm   = w >> 1;
    const int wn   = w & 1;

    auto issue = [&](int kt, int s) {
        const int ko = kt * 64;
        const uint32_t sA = sbase + (uint32_t)(s * 256 * SLDH) * 2;
        const uint32_t sB = sA + (uint32_t)(128 * SLDH) * 2;
        #pragma unroll
        for (int it = 0; it < 4; it++) {
            const int idx = tid + it * 256;
            const int r = idx >> 3, q = (idx & 7) * 8;
            cp16(sA + (uint32_t)(r * SLDH + q) * 2,
                 A + (size_t)(m0 + r) * E_ + ko + q);
            cp16(sB + (uint32_t)(r * SLDH + q) * 2,
                 Bw + (size_t)(n0 + r) * E_ + ko + q);
        }
        CP_COMMIT();
    };

    wmma::fragment<wmma::accumulator, 16, 16, 16, float> acc[2][4];
    #pragma unroll
    for (int i = 0; i < 2; i++)
        #pragma unroll
        for (int j = 0; j < 4; j++)
            wmma::fill_fragment(acc[i][j], 0.0f);

    constexpr int nk = E_ / 64;
    issue(0, 0);
    issue(1, 1);

    for (int kt = 0; kt < nk; kt++) {
        if (kt == nk - 1) { CP_WAIT0(); } else { CP_WAIT1(); }
        __syncthreads();
        if (kt + 2 < nk) issue(kt + 2, (kt + 2) % 3);

        const int s = kt % 3;
        const __half* As_ = smh + s * 256 * SLDH + wm * 32 * SLDH;
        const __half* Bs_ = smh + s * 256 * SLDH + 128 * SLDH + wn * 64 * SLDH;

        #pragma unroll
        for (int ks = 0; ks < 4; ks++) {
            wmma::fragment<wmma::matrix_a, 16, 16, 16, __half,
                           wmma::row_major> af[2];
            wmma::fragment<wmma::matrix_b, 16, 16, 16, __half,
                           wmma::col_major> bf[4];
            #pragma unroll
            for (int i = 0; i < 2; i++)
                wmma::load_matrix_sync(af[i], As_ + i * 16 * SLDH + ks * 16, SLDH);
            #pragma unroll
            for (int j = 0; j < 4; j++)
                wmma::load_matrix_sync(bf[j], Bs_ + j * 16 * SLDH + ks * 16, SLDH);
            #pragma unroll
            for (int i = 0; i < 2; i++)
                #pragma unroll
                for (int j = 0; j < 4; j++)
                    wmma::mma_sync(acc[i][j], af[i], bf[j], acc[i][j]);
        }
    }

    __syncthreads();
    float* stg = (float*)smh + w * 32 * 68;
    #pragma unroll
    for (int i = 0; i < 2; i++)
        #pragma unroll
        for (int j = 0; j < 4; j++)
            wmma::store_matrix_sync(stg + i * 16 * 68 + j * 16, acc[i][j],
                                    68, wmma::mem_row_major);
    __syncwarp();

    const int rowbase = m0 + wm * 32;
    const int colbase = n0 + wn * 64;
    for (int r = 0; r < 32; r++) {
        #pragma unroll
        for (int cb = 0; cb < 64; cb += 32) {
            const int c = cb + lane;
            const int col = colbase + c;
            const float v = (stg[r * 68 + c] + bias[col]) * scale;
            const size_t o = (size_t)(rowbase + r) * E_ + col;
            if (Cf) Cf[o] = v;
            else    Ch[o] = __float2half_rn(v);
        }
    }
}

// ---------------------------------------------------------------------------
// Big fp16 wmma GEMM (128x256 tile, 64x64 warp tiles — KV projection):
// 8 warps (2m x 4n), BK=64, 3-stage cp.async, 162 KB smem, 1 CTA/SM.
// MMA:LDSM ratio 4 (vs 2.67 in the 128-wide kernel). Half output + bias.
// blockIdx.x: [0,4) -> K weight, [4,8) -> V weight.
// ---------------------------------------------------------------------------
static constexpr int SMEM_BIG = 3 * 384 * SLDH * 2;   // 165888 B

__global__ __launch_bounds__(256) void kvproj_kernel(
    const __half* __restrict__ A,
    const __half* __restrict__ B0, const __half* __restrict__ B1,
    const float* __restrict__ bias0, const float* __restrict__ bias1,
    __half* __restrict__ Ch0, __half* __restrict__ Ch1)
{
    extern __shared__ __half smh[];
    const uint32_t sbase = smem_u32(smh);

    const __half* Bw   = B0;
    const float*  bias = bias0;
    __half*       Ch   = Ch0;
    int nblk = blockIdx.x;
    if (blockIdx.x >= 4) { Bw = B1; bias = bias1; Ch = Ch1; nblk = blockIdx.x - 4; }
    const int m0 = blockIdx.y * 128;
    const int n0 = nblk * 256;

    const int tid  = threadIdx.x;
    const int w    = tid >> 5;
    const int lane = tid & 31;
    const int wm   = w >> 2;   // 0..1 (64-row strips)
    const int wn   = w & 3;    // 0..3 (64-col strips)

    auto issue = [&](int kt, int s) {
        const int ko = kt * 64;
        const uint32_t sA = sbase + (uint32_t)(s * 384 * SLDH) * 2;
        const uint32_t sB = sA + (uint32_t)(128 * SLDH) * 2;
        #pragma unroll
        for (int it = 0; it < 4; it++) {      // A: 128 rows x 8 chunks
            const int idx = tid + it * 256;
            const int r = idx >> 3, q = (idx & 7) * 8;
            cp16(sA + (uint32_t)(r * SLDH + q) * 2,
                 A + (size_t)(m0 + r) * E_ + ko + q);
        }
        #pragma unroll
        for (int it = 0; it < 8; it++) {      // B: 256 rows x 8 chunks
            const int idx = tid + it * 256;
            const int r = idx >> 3, q = (idx & 7) * 8;
            cp16(sB + (uint32_t)(r * SLDH + q) * 2,
                 Bw + (size_t)(n0 + r) * E_ + ko + q);
        }
        CP_COMMIT();
    };

    wmma::fragment<wmma::accumulator, 16, 16, 16, float> acc[4][4];
    #pragma unroll
    for (int i = 0; i < 4; i++)
        #pragma unroll
        for (int j = 0; j < 4; j++)
            wmma::fill_fragment(acc[i][j], 0.0f);

    constexpr int nk = E_ / 64;  // 16
    issue(0, 0);
    issue(1, 1);

    for (int kt = 0; kt < nk; kt++) {
        if (kt == nk - 1) { CP_WAIT0(); } else { CP_WAIT1(); }
        __syncthreads();
        if (kt + 2 < nk) issue(kt + 2, (kt + 2) % 3);

        const int s = kt % 3;
        const __half* As_ = smh + s * 384 * SLDH + wm * 64 * SLDH;
        const __half* Bs_ = smh + s * 384 * SLDH + 128 * SLDH + wn * 64 * SLDH;

        #pragma unroll
        for (int ks = 0; ks < 4; ks++) {
            wmma::fragment<wmma::matrix_a, 16, 16, 16, __half,
                           wmma::row_major> af[4];
            wmma::fragment<wmma::matrix_b, 16, 16, 16, __half,
                           wmma::col_major> bf[4];
            #pragma unroll
            for (int i = 0; i < 4; i++)
                wmma::load_matrix_sync(af[i], As_ + i * 16 * SLDH + ks * 16, SLDH);
            #pragma unroll
            for (int j = 0; j < 4; j++)
                wmma::load_matrix_sync(bf[j], Bs_ + j * 16 * SLDH + ks * 16, SLDH);
            #pragma unroll
            for (int i = 0; i < 4; i++)
                #pragma unroll
                for (int j = 0; j < 4; j++)
                    wmma::mma_sync(acc[i][j], af[i], bf[j], acc[i][j]);
        }
    }

    // Epilogue: per-warp float staging (64x68), coalesced half write.
    __syncthreads();
    float* stg = (float*)smh + w * 64 * 68;
    #pragma unroll
    for (int i = 0; i < 4; i++)
        #pragma unroll
        for (int j = 0; j < 4; j++)
            wmma::store_matrix_sync(stg + i * 16 * 68 + j * 16, acc[i][j],
                                    68, wmma::mem_row_major);
    __syncwarp();

    const int rowbase = m0 + wm * 64;
    const int colbase = n0 + wn * 64;
    for (int r = 0; r < 64; r++) {
        #pragma unroll
        for (int cb = 0; cb < 64; cb += 32) {
            const int c = cb + lane;
            const int col = colbase + c;
            const float v = stg[r * 68 + c] + bias[col];
            Ch[(size_t)(rowbase + r) * E_ + col] = __float2half_rn(v);
        }
    }
}

// ---------------------------------------------------------------------------
// Fused flash attention (fp16 wmma). Triple-buffered K/V slots: the slot
// written at iter i was last consumed at iter i-2 (>=3 syncs ago), so the
// leading per-iteration __syncthreads is gone (3 syncs/iter instead of 4).
// Grid (T/64, B*H)=256 CTAs, 256 threads, 2 CTAs/SM (~106.5 KB smem).
// ---------------------------------------------------------------------------
static constexpr int HLD = 72;   // half-tile stride
static constexpr int FLD = 68;   // float-tile stride
static constexpr int OF_Q = 0;                    // 64 x 72
static constexpr int OF_K = OF_Q + 64 * HLD;      // 3 x 64 x 72
static constexpr int OF_V = OF_K + 3 * 64 * HLD;  // 3 x 64 x 72
static constexpr int OF_P = OF_V + 3 * 64 * HLD;  // 64 x 72
static constexpr int HEND = OF_P + 64 * HLD;      // 36864 halves
static constexpr int OF_S = 0;                    // 64 x 68 floats
static constexpr int OF_O = OF_S + 64 * FLD;
static constexpr int OF_L = OF_O + 64 * FLD;
static constexpr int OF_LI = OF_L + 64;
static constexpr int FLASH_SMEM = HEND * 2 + (OF_LI + 64) * 4;  // 109056 B

__global__ __launch_bounds__(256, 2) void flash_kernel()
{
    extern __shared__ __half smh[];
    const uint32_t sbase = smem_u32(smh);
    __half* Qs = smh + OF_Q;
    __half* Kh = smh + OF_K;
    __half* Vh = smh + OF_V;
    __half* Ps = smh + OF_P;
    float*  Sf = (float*)(smh + HEND);
    float*  Ss = Sf + OF_S;
    float*  Os = Sf + OF_O;
    float*  Lr = Sf + OF_L;
    float*  Li = Sf + OF_LI;

    const int t0 = blockIdx.x * 64;
    const int z  = blockIdx.y;       // b*H + h
    const int b  = z / H_;
    const int h  = z % H_;

    const int tid = threadIdx.x;
    const int w   = tid >> 5;
    const int wm  = w & 1;           // 0..1 (m strips of 32)
    const int wn  = w >> 1;          // 0..3 (n strips of 16)

    auto issue_kv = [&](int i, int slot) {
        const int c  = i >> 4;
        const int k0 = (i & 15) * 64;
        const __half* Kb = h_K + (size_t)(b * C_ + c) * K_ * E_ + h * 64;
        const __half* Vb = h_V + (size_t)(b * C_ + c) * K_ * E_ + h * 64;
        const uint32_t sk = sbase + (uint32_t)(OF_K + slot * 64 * HLD) * 2;
        const uint32_t sv = sbase + (uint32_t)(OF_V + slot * 64 * HLD) * 2;
        #pragma unroll
        for (int it = 0; it < 2; it++) {
            const int idx = tid + it * 256;
            const int r = idx >> 3, q = (idx & 7) * 8;
            const size_t go = (size_t)(k0 + r) * E_ + q;
            cp16(sk + (uint32_t)(r * HLD + q) * 2, Kb + go);
            cp16(sv + (uint32_t)(r * HLD + q) * 2, Vb + go);
        }
        CP_COMMIT();
    };

    // Prologue: Q tile + first K/V tile committed as group 0.
    {
        const __half* Qp = h_Q + (size_t)(b * T_ + t0) * E_ + h * 64;
        #pragma unroll
        for (int it = 0; it < 2; it++) {
            const int idx = tid + it * 256;
            const int r = idx >> 3, q = (idx & 7) * 8;
            cp16(sbase + (uint32_t)(OF_Q + r * HLD + q) * 2,
                 Qp + (size_t)r * E_ + q);
        }
        issue_kv(0, 0);
    }

    wmma::fragment<wmma::accumulator, 16, 16, 16, float> oacc[2];
    #pragma unroll
    for (int i = 0; i < 2; i++) wmma::fill_fragment(oacc[i], 0.0f);

    for (int i = 0; i < C_ * 16; i++) {
        const int kt   = i & 15;
        const int c    = i >> 4;
        const int slot = i % 3;

        // Prefetch next tile into slot (i+1)%3 — consumed at i-2, safe.
        if (i + 1 < C_ * 16) { issue_kv(i + 1, (i + 1) % 3); CP_WAIT1(); }
        else                 { CP_WAIT0(); }
        __syncthreads();                       // cp.async data visible

        // S = Q K^T : warp tile 32x16
        {
            wmma::fragment<wmma::accumulator, 16, 16, 16, float> sacc[2];
            #pragma unroll
            for (int ii = 0; ii < 2; ii++) wmma::fill_fragment(sacc[ii], 0.0f);
            const __half* Kb_ = Kh + slot * 64 * HLD + wn * 16 * HLD;
            #pragma unroll
            for (int ks = 0; ks < 4; ks++) {
                wmma::fragment<wmma::matrix_a, 16, 16, 16, __half,
                               wmma::row_major> af[2];
                wmma::fragment<wmma::matrix_b, 16, 16, 16, __half,
                               wmma::col_major> bf;
                #pragma unroll
                for (int ii = 0; ii < 2; ii++)
                    wmma::load_matrix_sync(
                        af[ii], Qs + (wm * 32 + ii * 16) * HLD + ks * 16, HLD);
                wmma::load_matrix_sync(bf, Kb_ + ks * 16, HLD);
                #pragma unroll
                for (int ii = 0; ii < 2; ii++)
                    wmma::mma_sync(sacc[ii], af[ii], bf, sacc[ii]);
            }
            #pragma unroll
            for (int ii = 0; ii < 2; ii++)
                wmma::store_matrix_sync(
                    Ss + (wm * 32 + ii * 16) * FLD + wn * 16, sacc[ii],
                    FLD, wmma::mem_row_major);
        }
        __syncthreads();

        // P = half(exp(S)) into Ps; row sums of the ROUNDED values.
        {
            const int row = tid >> 2;
            const int q   = tid & 3;
            const float* sr = Ss + row * FLD + q * 16;
            __half* pr = Ps + row * HLD + q * 16;
            float p = 0.0f;
            #pragma unroll
            for (int j = 0; j < 4; j++) {
                float4 v = *(const float4*)(sr + j * 4);
                __half2 e01 = __floats2half2_rn(__expf(v.x), __expf(v.y));
                __half2 e23 = __floats2half2_rn(__expf(v.z), __expf(v.w));
                *(__half2*)(pr + j * 4)     = e01;
                *(__half2*)(pr + j * 4 + 2) = e23;
                float2 f01 = __half22float2(e01);
                float2 f23 = __half22float2(e23);
                p += f01.x + f01.y + f23.x + f23.y;
            }
            p += __shfl_xor_sync(0xffffffffu, p, 1);
            p += __shfl_xor_sync(0xffffffffu, p, 2);
            if (q == 0) Lr[row] = (kt == 0) ? p : Lr[row] + p;
        }
        __syncthreads();

        // O_c += P V : warp tile 32x16
        {
            const __half* Vb_ = Vh + slot * 64 * HLD + wn * 16;
            #pragma unroll
            for (int ks = 0; ks < 4; ks++) {
                wmma::fragment<wmma::matrix_a, 16, 16, 16, __half,
                               wmma::row_major> af[2];
                wmma::fragment<wmma::matrix_b, 16, 16, 16, __half,
                               wmma::row_major> bf;
                #pragma unroll
                for (int ii = 0; ii < 2; ii++)
                    wmma::load_matrix_sync(
                        af[ii], Ps + (wm * 32 + ii * 16) * HLD + ks * 16, HLD);
                wmma::load_matrix_sync(bf, Vb_ + (ks * 16) * HLD, HLD);
                #pragma unroll
                for (int ii = 0; ii < 2; ii++)
                    wmma::mma_sync(oacc[ii], af[ii], bf, oacc[ii]);
            }
        }

        // Channel end: fold O_c/(l*C) into Os.
        if (kt == 15) {
            __syncthreads();   // all warps done with Ss/Ps
            #pragma unroll
            for (int ii = 0; ii < 2; ii++)
                wmma::store_matrix_sync(
                    Ss + (wm * 32 + ii * 16) * FLD + wn * 16, oacc[ii],
                    FLD, wmma::mem_row_major);
            if (tid < 64) Li[tid] = (1.0f / (float)C_) / Lr[tid];
            #pragma unroll
            for (int ii = 0; ii < 2; ii++) wmma::fill_fragment(oacc[ii], 0.0f);
            __syncthreads();
            for (int e = tid; e < 64 * 64; e += 256) {
                const int r = e >> 6, d = e & 63;
                const float contrib = Ss[r * FLD + d] * Li[r];
                Os[r * FLD + d] = (c == 0) ? contrib : Os[r * FLD + d] + contrib;
            }
        }
    }

    // Writeback O as half for the O-projection.
    __syncthreads();
    {
        __half* Ap = h_attn + (size_t)(b * T_ + t0) * E_ + h * 64;
        for (int e = tid; e < 64 * 64; e += 256) {
            const int r = e >> 6, d = e & 63;
            Ap[(size_t)r * E_ + d] = __float2half_rn(Os[r * FLD + d]);
        }
    }
}

// ---------------------------------------------------------------------------
// Launch
// ---------------------------------------------------------------------------
extern "C" void kernel_launch(void* const* d_in, const int* in_sizes, int n_in,
                              void* d_out, int out_size)
{
    const float* HS  = (const float*)d_in[0];
    const float* KVS = (const float*)d_in[1];
    const float* Wq  = (const float*)d_in[2];
    const float* bq  = (const float*)d_in[3];
    const float* Wk  = (const float*)d_in[4];
    const float* bk  = (const float*)d_in[5];
    const float* Wv  = (const float*)d_in[6];
    const float* bv  = (const float*)d_in[7];
    const float* Wo  = (const float*)d_in[8];
    const float* bo  = (const float*)d_in[9];
    float* out = (float*)d_out;

    cudaFuncSetAttribute(proj_kernel,   cudaFuncAttributeMaxDynamicSharedMemorySize, SMEM_PROJ);
    cudaFuncSetAttribute(kvproj_kernel, cudaFuncAttributeMaxDynamicSharedMemorySize, SMEM_BIG);
    cudaFuncSetAttribute(flash_kernel,  cudaFuncAttributeMaxDynamicSharedMemorySize, FLASH_SMEM);

    __half *pHS, *pKV, *pWq, *pWk, *pWv, *pWo, *pQ, *pK, *pV, *pA;
    cudaGetSymbolAddress((void**)&pHS, h_HS);
    cudaGetSymbolAddress((void**)&pKV, h_KV);
    cudaGetSymbolAddress((void**)&pWq, h_Wq);
    cudaGetSymbolAddress((void**)&pWk, h_Wk);
    cudaGetSymbolAddress((void**)&pWv, h_Wv);
    cudaGetSymbolAddress((void**)&pWo, h_Wo);
    cudaGetSymbolAddress((void**)&pQ,  h_Q);
    cudaGetSymbolAddress((void**)&pK,  h_K);
    cudaGetSymbolAddress((void**)&pV,  h_V);
    cudaGetSymbolAddress((void**)&pA,  h_attn);

    // 0) Convert all GEMM operands to fp16 (RN) — single launch
    f2h_all<<<(N4_TOTAL + 255) / 256, 256>>>(
        (const float4*)HS, (const float4*)KVS,
        (const float4*)Wq, (const float4*)Wk, (const float4*)Wv, (const float4*)Wo,
        (uint2*)pHS, (uint2*)pKV, (uint2*)pWq, (uint2*)pWk, (uint2*)pWv, (uint2*)pWo);

    // 1) Q projection (scaled, half output)
    proj_kernel<<<dim3(E_ / 128, (B_ * T_) / 128), 256, SMEM_PROJ>>>(
        pHS, pWq, bq, pQ, nullptr, 0.125f);

    // 2) K and V projections merged, 128x256 tiles
    kvproj_kernel<<<dim3(8, (B_ * C_ * K_) / 128), 256, SMEM_BIG>>>(
        pKV, pWk, pWv, bk, bv, pK, pV);

    // 3) Fused attention (scores + softmax + PV + channel pooling)
    flash_kernel<<<dim3(T_ / 64, B_ * H_), 256, FLASH_SMEM>>>();

    // 4) Output projection (float final output)
    proj_kernel<<<dim3(E_ / 128, (B_ * T_) / 128), 256, SMEM_PROJ>>>(
        pA, pWo, bo, nullptr, out, 1.0f);
}

// round 13
// speedup vs baseline: 1.3326x; 1.3326x over previous
#include <cuda_runtime.h>
#include <mma.h>
#include <cuda_fp16.h>
#include <cstdint>

using namespace nvcuda;

// Problem constants
static constexpr int B_ = 2;
static constexpr int C_ = 4;
static constexpr int T_ = 512;
static constexpr int K_ = 1024;
static constexpr int E_ = 1024;
static constexpr int H_ = 16;
static constexpr int D_ = 64;

// Scratch (device globals, allocation-free). All GEMM operands in fp16.
__device__ __half h_HS[B_ * T_ * E_];
__device__ __half h_KV[B_ * C_ * K_ * E_];
__device__ __half h_Wq[E_ * E_];
__device__ __half h_Wk[E_ * E_];
__device__ __half h_Wv[E_ * E_];
__device__ __half h_Wo[E_ * E_];
__device__ __half h_Q[B_ * T_ * E_];
__device__ __half h_K[B_ * C_ * K_ * E_];
__device__ __half h_V[B_ * C_ * K_ * E_];
__device__ __half h_attn[B_ * T_ * E_];

// ---------------------------------------------------------------------------
// Helpers
// ---------------------------------------------------------------------------
__device__ __forceinline__ uint32_t smem_u32(const void* p) {
    uint32_t a;
    asm("{ .reg .u64 t; cvta.to.shared.u64 t, %1; cvt.u32.u64 %0, t; }"
        : "=r"(a) : "l"(p));
    return a;
}

__device__ __forceinline__ void cp16(uint32_t saddr, const void* g) {
    asm volatile("cp.async.cg.shared.global [%0], [%1], 16;"
                 :: "r"(saddr), "l"(g) : "memory");
}
#define CP_COMMIT() asm volatile("cp.async.commit_group;" ::: "memory")
#define CP_WAIT0()  asm volatile("cp.async.wait_group 0;" ::: "memory")
#define CP_WAIT1()  asm volatile("cp.async.wait_group 1;" ::: "memory")

__device__ __forceinline__ void ldsm_x4(uint32_t (&r)[4], uint32_t a) {
    asm volatile("ldmatrix.sync.aligned.m8n8.x4.shared.b16 {%0,%1,%2,%3}, [%4];"
                 : "=r"(r[0]), "=r"(r[1]), "=r"(r[2]), "=r"(r[3]) : "r"(a));
}
__device__ __forceinline__ void ldsm_x4t(uint32_t (&r)[4], uint32_t a) {
    asm volatile("ldmatrix.sync.aligned.m8n8.x4.trans.shared.b16 {%0,%1,%2,%3}, [%4];"
                 : "=r"(r[0]), "=r"(r[1]), "=r"(r[2]), "=r"(r[3]) : "r"(a));
}
__device__ __forceinline__ void mma16816(float (&c)[4],
                                         uint32_t a0, uint32_t a1, uint32_t a2, uint32_t a3,
                                         uint32_t b0, uint32_t b1) {
    asm volatile(
        "mma.sync.aligned.m16n8k16.row.col.f32.f16.f16.f32 "
        "{%0,%1,%2,%3},{%4,%5,%6,%7},{%8,%9},{%0,%1,%2,%3};"
        : "+f"(c[0]), "+f"(c[1]), "+f"(c[2]), "+f"(c[3])
        : "r"(a0), "r"(a1), "r"(a2), "r"(a3), "r"(b0), "r"(b1));
}

// ---------------------------------------------------------------------------
// Fused float -> fp16 (RN) conversion for all six operand tensors, one launch.
// ---------------------------------------------------------------------------
static constexpr int N4_HS = (B_ * T_ * E_) / 4;
static constexpr int N4_KV = (B_ * C_ * K_ * E_) / 4;
static constexpr int N4_W  = (E_ * E_) / 4;
static constexpr int N4_TOTAL = N4_HS + N4_KV + 4 * N4_W;

__global__ void f2h_all(const float4* __restrict__ hs,
                        const float4* __restrict__ kvs,
                        const float4* __restrict__ wq, const float4* __restrict__ wk,
                        const float4* __restrict__ wv, const float4* __restrict__ wo,
                        uint2* __restrict__ ohs, uint2* __restrict__ okv,
                        uint2* __restrict__ owq, uint2* __restrict__ owk,
                        uint2* __restrict__ owv, uint2* __restrict__ owo)
{
    int i = blockIdx.x * 256 + threadIdx.x;
    if (i >= N4_TOTAL) return;
    const float4* src;
    uint2* dst;
    int j = i;
    if (j < N4_HS)                 { src = hs;  dst = ohs; }
    else if ((j -= N4_HS) < N4_KV) { src = kvs; dst = okv; }
    else if ((j -= N4_KV) < N4_W)  { src = wq;  dst = owq; }
    else if ((j -= N4_W) < N4_W)   { src = wk;  dst = owk; }
    else if ((j -= N4_W) < N4_W)   { src = wv;  dst = owv; }
    else { j -= N4_W;                src = wo;  dst = owo; }
    float4 v = src[j];
    __half2 a = __floats2half2_rn(v.x, v.y);
    __half2 b = __floats2half2_rn(v.z, v.w);
    dst[j] = make_uint2(*(uint32_t*)&a, *(uint32_t*)&b);
}

// ---------------------------------------------------------------------------
// fp16 wmma projection GEMM (128x128 tile) — exact R10-proven version.
// ---------------------------------------------------------------------------
static constexpr int SLDH = 72;
static constexpr int SMEM_PROJ = 3 * 256 * SLDH * 2;   // 110592 B

__global__ __launch_bounds__(256, 2) void proj_kernel(
    const __half* __restrict__ A,
    const __half* __restrict__ B0, const __half* __restrict__ B1,
    const float* __restrict__ bias0, const float* __restrict__ bias1,
    __half* __restrict__ Ch0, __half* __restrict__ Ch1,
    float* __restrict__ Cf,
    float scale, int nx_half)
{
    extern __shared__ __half smh[];
    const uint32_t sbase = smem_u32(smh);

    const __half* Bw   = B0;
    const float*  bias = bias0;
    __half*       Ch   = Ch0;
    int nblk = blockIdx.x;
    if (nx_half && blockIdx.x >= nx_half) {
        Bw = B1; bias = bias1; Ch = Ch1; nblk = blockIdx.x - nx_half;
    }
    const int m0 = blockIdx.y * 128;
    const int n0 = nblk * 128;

    const int tid  = threadIdx.x;
    const int w    = tid >> 5;
    const int lane = tid & 31;
    const int wm   = w >> 1;
    const int wn   = w & 1;

    auto issue = [&](int kt, int s) {
        const int ko = kt * 64;
        const uint32_t sA = sbase + (uint32_t)(s * 256 * SLDH) * 2;
        const uint32_t sB = sA + (uint32_t)(128 * SLDH) * 2;
        #pragma unroll
        for (int it = 0; it < 4; it++) {
            const int idx = tid + it * 256;
            const int r = idx >> 3, q = (idx & 7) * 8;
            cp16(sA + (uint32_t)(r * SLDH + q) * 2,
                 A + (size_t)(m0 + r) * E_ + ko + q);
            cp16(sB + (uint32_t)(r * SLDH + q) * 2,
                 Bw + (size_t)(n0 + r) * E_ + ko + q);
        }
        CP_COMMIT();
    };

    wmma::fragment<wmma::accumulator, 16, 16, 16, float> acc[2][4];
    #pragma unroll
    for (int i = 0; i < 2; i++)
        #pragma unroll
        for (int j = 0; j < 4; j++)
            wmma::fill_fragment(acc[i][j], 0.0f);

    constexpr int nk = E_ / 64;
    issue(0, 0);
    issue(1, 1);

    for (int kt = 0; kt < nk; kt++) {
        if (kt == nk - 1) { CP_WAIT0(); } else { CP_WAIT1(); }
        __syncthreads();
        if (kt + 2 < nk) issue(kt + 2, (kt + 2) % 3);

        const int s = kt % 3;
        const __half* As_ = smh + s * 256 * SLDH + wm * 32 * SLDH;
        const __half* Bs_ = smh + s * 256 * SLDH + 128 * SLDH + wn * 64 * SLDH;

        #pragma unroll
        for (int ks = 0; ks < 4; ks++) {
            wmma::fragment<wmma::matrix_a, 16, 16, 16, __half,
                           wmma::row_major> af[2];
            wmma::fragment<wmma::matrix_b, 16, 16, 16, __half,
                           wmma::col_major> bf[4];
            #pragma unroll
            for (int i = 0; i < 2; i++)
                wmma::load_matrix_sync(af[i], As_ + i * 16 * SLDH + ks * 16, SLDH);
            #pragma unroll
            for (int j = 0; j < 4; j++)
                wmma::load_matrix_sync(bf[j], Bs_ + j * 16 * SLDH + ks * 16, SLDH);
            #pragma unroll
            for (int i = 0; i < 2; i++)
                #pragma unroll
                for (int j = 0; j < 4; j++)
                    wmma::mma_sync(acc[i][j], af[i], bf[j], acc[i][j]);
        }
    }

    __syncthreads();
    float* stg = (float*)smh + w * 32 * 68;
    #pragma unroll
    for (int i = 0; i < 2; i++)
        #pragma unroll
        for (int j = 0; j < 4; j++)
            wmma::store_matrix_sync(stg + i * 16 * 68 + j * 16, acc[i][j],
                                    68, wmma::mem_row_major);
    __syncwarp();

    const int rowbase = m0 + wm * 32;
    const int colbase = n0 + wn * 64;
    for (int r = 0; r < 32; r++) {
        #pragma unroll
        for (int cb = 0; cb < 64; cb += 32) {
            const int c = cb + lane;
            const int col = colbase + c;
            const float v = (stg[r * 68 + c] + bias[col]) * scale;
            const size_t o = (size_t)(rowbase + r) * E_ + col;
            if (Cf) Cf[o] = v;
            else    Ch[o] = __float2half_rn(v);
        }
    }
}

// ---------------------------------------------------------------------------
// Fused flash attention v3: raw mma.m16n8k16 + ldmatrix, register-resident P.
// Grid (T/64, B*H)=256 CTAs, 256 threads = 2 k-groups x 4 t-warps, 2 CTAs/SM.
// Per group: private double-buffered K/V slots, group-scoped named barriers.
// S acc frags -> exp+pack(half2) in regs -> fed directly as PV A operand
// (block pair 2m,2m+1 = one k16 A fragment; layout algebra per PTX spec).
// l merged per channel via SMEM; O accumulated per channel into shared Osm
// (group adds serialized). No max subtraction (scores bounded).
// ---------------------------------------------------------------------------
static constexpr int HLD  = 72;
static constexpr int SLOTH = 2 * 64 * HLD;          // K+V halves per slot
static constexpr int OF_Q  = 4 * SLOTH;             // after 4 slots
static constexpr int HEND  = OF_Q + 64 * HLD;       // 41472 halves
static constexpr int OSLD  = 66;
static constexpr int FLASH_SMEM = HEND * 2 + (128 + 64 * OSLD) * 4;  // 100352 B

__global__ __launch_bounds__(256, 2) void flash_kernel()
{
    extern __shared__ __half smh[];
    const uint32_t sbase = smem_u32(smh);
    float* Lr  = (float*)(smh + HEND);   // [2][64]
    float* Osm = Lr + 128;               // [64][OSLD]

    const int t0 = blockIdx.x * 64;
    const int z  = blockIdx.y;
    const int b  = z / H_;
    const int h  = z % H_;

    const int tid  = threadIdx.x;
    const int grp  = tid >> 7;           // 0,1
    const int gtid = tid & 127;
    const int w    = gtid >> 5;          // t-warp in group
    const int lane = tid & 31;
    const int qg   = lane >> 2;          // 0..7
    const int qt   = lane & 3;           // 0..3

    auto issue_kv = [&](int p) {
        const int c  = p >> 3;
        const int k0 = ((grp << 3) + (p & 7)) << 6;
        const int slot = (grp << 1) + (p & 1);
        const __half* Kb = h_K + ((size_t)(b * C_ + c) * K_ + k0) * E_ + h * 64;
        const __half* Vb = h_V + ((size_t)(b * C_ + c) * K_ + k0) * E_ + h * 64;
        const uint32_t sk = sbase + (uint32_t)(slot * SLOTH) * 2;
        const uint32_t sv = sk + (uint32_t)(64 * HLD) * 2;
        #pragma unroll
        for (int it = 0; it < 4; it++) {
            const int idx = gtid + it * 128;
            const int r = idx >> 3, q = (idx & 7) * 8;
            cp16(sk + (uint32_t)(r * HLD + q) * 2, Kb + (size_t)r * E_ + q);
            cp16(sv + (uint32_t)(r * HLD + q) * 2, Vb + (size_t)r * E_ + q);
        }
        CP_COMMIT();
    };

    // Prologue: Q (all threads) then first K/V tile (per group).
    {
        const __half* Qp = h_Q + (size_t)(b * T_ + t0) * E_ + h * 64;
        #pragma unroll
        for (int it = 0; it < 2; it++) {
            const int idx = tid + it * 256;
            const int r = idx >> 3, q = (idx & 7) * 8;
            cp16(sbase + (uint32_t)(OF_Q + r * HLD + q) * 2,
                 Qp + (size_t)r * E_ + q);
        }
        CP_COMMIT();
        issue_kv(0);
        CP_WAIT1();          // Q arrived
        __syncthreads();
    }

    // Q A-fragments (4 k16 chunks x 4 regs), rows = w*16 .. +15
    uint32_t Qf[4][4];
    {
        const int row = w * 16 + (lane & 15);
        const int dof = (lane >> 4) << 3;
        #pragma unroll
        for (int m = 0; m < 4; m++)
            ldsm_x4(Qf[m], sbase + (uint32_t)(OF_Q + row * HLD + m * 16 + dof) * 2);
    }

    float Oc[8][4];
    #pragma unroll
    for (int j = 0; j < 8; j++)
        #pragma unroll
        for (int r = 0; r < 4; r++) Oc[j][r] = 0.0f;
    float lc0 = 0.0f, lc1 = 0.0f;
    const int barid = grp + 1;

    const int krow_ = (lane & 7);
    const int kdof_ = (lane >> 3) << 3;      // 0,8,16,24
    const int vrow_ = (lane & 15);
    const int vdof_ = (lane >> 4) << 3;      // 0,8

    for (int p = 0; p < 32; p++) {
        CP_WAIT0();
        asm volatile("bar.sync %0, 128;" :: "r"(barid) : "memory");
        if (p + 1 < 32) issue_kv(p + 1);

        const int slot = (grp << 1) + (p & 1);
        const uint32_t skb = sbase + (uint32_t)(slot * SLOTH) * 2;
        const uint32_t svb = skb + (uint32_t)(64 * HLD) * 2;

        // S = Q K^T per n8 block j; exp+pack to P in registers.
        uint32_t Pr[8][2];
        #pragma unroll
        for (int j = 0; j < 8; j++) {
            float S[4] = {0.0f, 0.0f, 0.0f, 0.0f};
            const uint32_t ka = skb + (uint32_t)((j * 8 + krow_) * HLD + kdof_) * 2;
            #pragma unroll
            for (int m2 = 0; m2 < 2; m2++) {
                uint32_t kb[4];
                ldsm_x4(kb, ka + (uint32_t)(m2 * 32) * 2);
                mma16816(S, Qf[2 * m2][0], Qf[2 * m2][1], Qf[2 * m2][2], Qf[2 * m2][3],
                         kb[0], kb[1]);
                mma16816(S, Qf[2 * m2 + 1][0], Qf[2 * m2 + 1][1], Qf[2 * m2 + 1][2],
                         Qf[2 * m2 + 1][3], kb[2], kb[3]);
            }
            __half2 e01 = __floats2half2_rn(__expf(S[0]), __expf(S[1]));
            __half2 e23 = __floats2half2_rn(__expf(S[2]), __expf(S[3]));
            Pr[j][0] = *(uint32_t*)&e01;
            Pr[j][1] = *(uint32_t*)&e23;
            float2 f01 = __half22float2(e01);
            float2 f23 = __half22float2(e23);
            lc0 += f01.x + f01.y;        // sums of ROUNDED P: bias cancels in O/l
            lc1 += f23.x + f23.y;
        }

        // O_c += P V (P regs fed directly as A fragments).
        #pragma unroll
        for (int m = 0; m < 4; m++) {
            const uint32_t va = svb + (uint32_t)((m * 16 + vrow_) * HLD + vdof_) * 2;
            #pragma unroll
            for (int j2 = 0; j2 < 4; j2++) {
                uint32_t vb[4];
                ldsm_x4t(vb, va + (uint32_t)(j2 * 16) * 2);
                mma16816(Oc[2 * j2], Pr[2 * m][0], Pr[2 * m][1],
                         Pr[2 * m + 1][0], Pr[2 * m + 1][1], vb[0], vb[1]);
                mma16816(Oc[2 * j2 + 1], Pr[2 * m][0], Pr[2 * m][1],
                         Pr[2 * m + 1][0], Pr[2 * m + 1][1], vb[2], vb[3]);
            }
        }

        // Channel end: merge l across groups, fold O_c/(l*C) into Osm.
        if ((p & 7) == 7) {
            const int c = p >> 3;
            float r0 = lc0;
            r0 += __shfl_xor_sync(0xffffffffu, r0, 1);
            r0 += __shfl_xor_sync(0xffffffffu, r0, 2);
            float r1 = lc1;
            r1 += __shfl_xor_sync(0xffffffffu, r1, 1);
            r1 += __shfl_xor_sync(0xffffffffu, r1, 2);
            if (qt == 0) {
                Lr[grp * 64 + w * 16 + qg]     = r0;
                Lr[grp * 64 + w * 16 + qg + 8] = r1;
            }
            __syncthreads();
            const float li0 = 1.0f / ((float)C_ * (Lr[w * 16 + qg] + Lr[64 + w * 16 + qg]));
            const float li1 = 1.0f / ((float)C_ * (Lr[w * 16 + qg + 8] + Lr[64 + w * 16 + qg + 8]));
            if (grp == 0) {
                #pragma unroll
                for (int j = 0; j < 8; j++) {
                    float* o0 = Osm + (w * 16 + qg) * OSLD + j * 8 + 2 * qt;
                    float* o1 = o0 + 8 * OSLD;
                    if (c == 0) {
                        o0[0] = Oc[j][0] * li0; o0[1] = Oc[j][1] * li0;
                        o1[0] = Oc[j][2] * li1; o1[1] = Oc[j][3] * li1;
                    } else {
                        o0[0] += Oc[j][0] * li0; o0[1] += Oc[j][1] * li0;
                        o1[0] += Oc[j][2] * li1; o1[1] += Oc[j][3] * li1;
                    }
                }
            }
            __syncthreads();
            if (grp == 1) {
                #pragma unroll
                for (int j = 0; j < 8; j++) {
                    float* o0 = Osm + (w * 16 + qg) * OSLD + j * 8 + 2 * qt;
                    float* o1 = o0 + 8 * OSLD;
                    o0[0] += Oc[j][0] * li0; o0[1] += Oc[j][1] * li0;
                    o1[0] += Oc[j][2] * li1; o1[1] += Oc[j][3] * li1;
                }
            }
            __syncthreads();
            #pragma unroll
            for (int j = 0; j < 8; j++)
                #pragma unroll
                for (int r = 0; r < 4; r++) Oc[j][r] = 0.0f;
            lc0 = lc1 = 0.0f;
        }
    }

    // Writeback O as half for the O-projection.
    {
        __half* Ap = h_attn + (size_t)(b * T_ + t0) * E_ + h * 64;
        for (int e = tid; e < 64 * 64; e += 256) {
            const int r = e >> 6, d = e & 63;
            Ap[(size_t)r * E_ + d] = __float2half_rn(Osm[r * OSLD + d]);
        }
    }
}

// ---------------------------------------------------------------------------
// Launch
// ---------------------------------------------------------------------------
extern "C" void kernel_launch(void* const* d_in, const int* in_sizes, int n_in,
                              void* d_out, int out_size)
{
    const float* HS  = (const float*)d_in[0];
    const float* KVS = (const float*)d_in[1];
    const float* Wq  = (const float*)d_in[2];
    const float* bq  = (const float*)d_in[3];
    const float* Wk  = (const float*)d_in[4];
    const float* bk  = (const float*)d_in[5];
    const float* Wv  = (const float*)d_in[6];
    const float* bv  = (const float*)d_in[7];
    const float* Wo  = (const float*)d_in[8];
    const float* bo  = (const float*)d_in[9];
    float* out = (float*)d_out;

    cudaFuncSetAttribute(proj_kernel,  cudaFuncAttributeMaxDynamicSharedMemorySize, SMEM_PROJ);
    cudaFuncSetAttribute(flash_kernel, cudaFuncAttributeMaxDynamicSharedMemorySize, FLASH_SMEM);

    __half *pHS, *pKV, *pWq, *pWk, *pWv, *pWo, *pQ, *pK, *pV, *pA;
    cudaGetSymbolAddress((void**)&pHS, h_HS);
    cudaGetSymbolAddress((void**)&pKV, h_KV);
    cudaGetSymbolAddress((void**)&pWq, h_Wq);
    cudaGetSymbolAddress((void**)&pWk, h_Wk);
    cudaGetSymbolAddress((void**)&pWv, h_Wv);
    cudaGetSymbolAddress((void**)&pWo, h_Wo);
    cudaGetSymbolAddress((void**)&pQ,  h_Q);
    cudaGetSymbolAddress((void**)&pK,  h_K);
    cudaGetSymbolAddress((void**)&pV,  h_V);
    cudaGetSymbolAddress((void**)&pA,  h_attn);

    // 0) Convert all GEMM operands to fp16 (RN) — single launch
    f2h_all<<<(N4_TOTAL + 255) / 256, 256>>>(
        (const float4*)HS, (const float4*)KVS,
        (const float4*)Wq, (const float4*)Wk, (const float4*)Wv, (const float4*)Wo,
        (uint2*)pHS, (uint2*)pKV, (uint2*)pWq, (uint2*)pWk, (uint2*)pWv, (uint2*)pWo);

    // 1) Q projection (scaled, half output)
    proj_kernel<<<dim3(E_ / 128, (B_ * T_) / 128), 256, SMEM_PROJ>>>(
        pHS, pWq, nullptr, bq, nullptr, pQ, nullptr, nullptr, 0.125f, 0);

    // 2) K and V projections merged (R10-proven config)
    proj_kernel<<<dim3(2 * E_ / 128, (B_ * C_ * K_) / 128), 256, SMEM_PROJ>>>(
        pKV, pWk, pWv, bk, bv, pK, pV, nullptr, 1.0f, E_ / 128);

    // 3) Fused attention (scores + softmax + PV + channel pooling)
    flash_kernel<<<dim3(T_ / 64, B_ * H_), 256, FLASH_SMEM>>>();

    // 4) Output projection (float final output)
    proj_kernel<<<dim3(E_ / 128, (B_ * T_) / 128), 256, SMEM_PROJ>>>(
        pA, pWo, nullptr, bo, nullptr, nullptr, nullptr, out, 1.0f, 0);
}

// round 14
// speedup vs baseline: 1.3592x; 1.0199x over previous
#include <cuda_runtime.h>
#include <mma.h>
#include <cuda_fp16.h>
#include <cstdint>

using namespace nvcuda;

// Problem constants
static constexpr int B_ = 2;
static constexpr int C_ = 4;
static constexpr int T_ = 512;
static constexpr int K_ = 1024;
static constexpr int E_ = 1024;
static constexpr int H_ = 16;
static constexpr int D_ = 64;

// Scratch (device globals, allocation-free). All GEMM operands in fp16.
__device__ __half h_HS[B_ * T_ * E_];
__device__ __half h_KV[B_ * C_ * K_ * E_];
__device__ __half h_Wq[E_ * E_];
__device__ __half h_Wk[E_ * E_];
__device__ __half h_Wv[E_ * E_];
__device__ __half h_Wo[E_ * E_];
__device__ __half h_Q[B_ * T_ * E_];
__device__ __half h_K[B_ * C_ * K_ * E_];
__device__ __half h_V[B_ * C_ * K_ * E_];
__device__ __half h_attn[B_ * T_ * E_];

// ---------------------------------------------------------------------------
// Helpers
// ---------------------------------------------------------------------------
__device__ __forceinline__ uint32_t smem_u32(const void* p) {
    uint32_t a;
    asm("{ .reg .u64 t; cvta.to.shared.u64 t, %1; cvt.u32.u64 %0, t; }"
        : "=r"(a) : "l"(p));
    return a;
}

__device__ __forceinline__ void cp16(uint32_t saddr, const void* g) {
    asm volatile("cp.async.cg.shared.global [%0], [%1], 16;"
                 :: "r"(saddr), "l"(g) : "memory");
}
#define CP_COMMIT() asm volatile("cp.async.commit_group;" ::: "memory")
#define CP_WAIT0()  asm volatile("cp.async.wait_group 0;" ::: "memory")
#define CP_WAIT1()  asm volatile("cp.async.wait_group 1;" ::: "memory")

__device__ __forceinline__ void ldsm_x4(uint32_t (&r)[4], uint32_t a) {
    asm volatile("ldmatrix.sync.aligned.m8n8.x4.shared.b16 {%0,%1,%2,%3}, [%4];"
                 : "=r"(r[0]), "=r"(r[1]), "=r"(r[2]), "=r"(r[3]) : "r"(a));
}
__device__ __forceinline__ void ldsm_x4t(uint32_t (&r)[4], uint32_t a) {
    asm volatile("ldmatrix.sync.aligned.m8n8.x4.trans.shared.b16 {%0,%1,%2,%3}, [%4];"
                 : "=r"(r[0]), "=r"(r[1]), "=r"(r[2]), "=r"(r[3]) : "r"(a));
}
__device__ __forceinline__ void mma16816(float (&c)[4],
                                         uint32_t a0, uint32_t a1, uint32_t a2, uint32_t a3,
                                         uint32_t b0, uint32_t b1) {
    asm volatile(
        "mma.sync.aligned.m16n8k16.row.col.f32.f16.f16.f32 "
        "{%0,%1,%2,%3},{%4,%5,%6,%7},{%8,%9},{%0,%1,%2,%3};"
        : "+f"(c[0]), "+f"(c[1]), "+f"(c[2]), "+f"(c[3])
        : "r"(a0), "r"(a1), "r"(a2), "r"(a3), "r"(b0), "r"(b1));
}

// ---------------------------------------------------------------------------
// Fused float -> fp16 (RN) conversion for all six operand tensors, one launch.
// ---------------------------------------------------------------------------
static constexpr int N4_HS = (B_ * T_ * E_) / 4;
static constexpr int N4_KV = (B_ * C_ * K_ * E_) / 4;
static constexpr int N4_W  = (E_ * E_) / 4;
static constexpr int N4_TOTAL = N4_HS + N4_KV + 4 * N4_W;

__global__ void f2h_all(const float4* __restrict__ hs,
                        const float4* __restrict__ kvs,
                        const float4* __restrict__ wq, const float4* __restrict__ wk,
                        const float4* __restrict__ wv, const float4* __restrict__ wo,
                        uint2* __restrict__ ohs, uint2* __restrict__ okv,
                        uint2* __restrict__ owq, uint2* __restrict__ owk,
                        uint2* __restrict__ owv, uint2* __restrict__ owo)
{
    int i = blockIdx.x * 256 + threadIdx.x;
    if (i >= N4_TOTAL) return;
    const float4* src;
    uint2* dst;
    int j = i;
    if (j < N4_HS)                 { src = hs;  dst = ohs; }
    else if ((j -= N4_HS) < N4_KV) { src = kvs; dst = okv; }
    else if ((j -= N4_KV) < N4_W)  { src = wq;  dst = owq; }
    else if ((j -= N4_W) < N4_W)   { src = wk;  dst = owk; }
    else if ((j -= N4_W) < N4_W)   { src = wv;  dst = owv; }
    else { j -= N4_W;                src = wo;  dst = owo; }
    float4 v = src[j];
    __half2 a = __floats2half2_rn(v.x, v.y);
    __half2 b = __floats2half2_rn(v.z, v.w);
    dst[j] = make_uint2(*(uint32_t*)&a, *(uint32_t*)&b);
}

// ---------------------------------------------------------------------------
// fp16 wmma projection GEMM tile body (128x128, R10/R13-proven config):
// BK=64, stride 72 halves, 3-stage cp.async, 8 warps (4m x 2n), 32x64 warp tile.
// ---------------------------------------------------------------------------
static constexpr int SLDH = 72;
static constexpr int SMEM_PROJ = 3 * 256 * SLDH * 2;   // 110592 B

__device__ __forceinline__ void proj_tile(
    const __half* __restrict__ A,
    const __half* __restrict__ Bw,
    const float* __restrict__ bias,
    __half* __restrict__ Ch, float* __restrict__ Cf,
    float scale, int m0, int n0, __half* smh)
{
    const uint32_t sbase = smem_u32(smh);

    const int tid  = threadIdx.x;
    const int w    = tid >> 5;
    const int lane = tid & 31;
    const int wm   = w >> 1;
    const int wn   = w & 1;

    auto issue = [&](int kt, int s) {
        const int ko = kt * 64;
        const uint32_t sA = sbase + (uint32_t)(s * 256 * SLDH) * 2;
        const uint32_t sB = sA + (uint32_t)(128 * SLDH) * 2;
        #pragma unroll
        for (int it = 0; it < 4; it++) {
            const int idx = tid + it * 256;
            const int r = idx >> 3, q = (idx & 7) * 8;
            cp16(sA + (uint32_t)(r * SLDH + q) * 2,
                 A + (size_t)(m0 + r) * E_ + ko + q);
            cp16(sB + (uint32_t)(r * SLDH + q) * 2,
                 Bw + (size_t)(n0 + r) * E_ + ko + q);
        }
        CP_COMMIT();
    };

    wmma::fragment<wmma::accumulator, 16, 16, 16, float> acc[2][4];
    #pragma unroll
    for (int i = 0; i < 2; i++)
        #pragma unroll
        for (int j = 0; j < 4; j++)
            wmma::fill_fragment(acc[i][j], 0.0f);

    constexpr int nk = E_ / 64;
    issue(0, 0);
    issue(1, 1);

    for (int kt = 0; kt < nk; kt++) {
        if (kt == nk - 1) { CP_WAIT0(); } else { CP_WAIT1(); }
        __syncthreads();
        if (kt + 2 < nk) issue(kt + 2, (kt + 2) % 3);

        const int s = kt % 3;
        const __half* As_ = smh + s * 256 * SLDH + wm * 32 * SLDH;
        const __half* Bs_ = smh + s * 256 * SLDH + 128 * SLDH + wn * 64 * SLDH;

        #pragma unroll
        for (int ks = 0; ks < 4; ks++) {
            wmma::fragment<wmma::matrix_a, 16, 16, 16, __half,
                           wmma::row_major> af[2];
            wmma::fragment<wmma::matrix_b, 16, 16, 16, __half,
                           wmma::col_major> bf[4];
            #pragma unroll
            for (int i = 0; i < 2; i++)
                wmma::load_matrix_sync(af[i], As_ + i * 16 * SLDH + ks * 16, SLDH);
            #pragma unroll
            for (int j = 0; j < 4; j++)
                wmma::load_matrix_sync(bf[j], Bs_ + j * 16 * SLDH + ks * 16, SLDH);
            #pragma unroll
            for (int i = 0; i < 2; i++)
                #pragma unroll
                for (int j = 0; j < 4; j++)
                    wmma::mma_sync(acc[i][j], af[i], bf[j], acc[i][j]);
        }
    }

    __syncthreads();
    float* stg = (float*)smh + w * 32 * 68;
    #pragma unroll
    for (int i = 0; i < 2; i++)
        #pragma unroll
        for (int j = 0; j < 4; j++)
            wmma::store_matrix_sync(stg + i * 16 * 68 + j * 16, acc[i][j],
                                    68, wmma::mem_row_major);
    __syncwarp();

    const int rowbase = m0 + wm * 32;
    const int colbase = n0 + wn * 64;
    for (int r = 0; r < 32; r++) {
        #pragma unroll
        for (int cb = 0; cb < 64; cb += 32) {
            const int c = cb + lane;
            const int col = colbase + c;
            const float v = (stg[r * 68 + c] + bias[col]) * scale;
            const size_t o = (size_t)(rowbase + r) * E_ + col;
            if (Cf) Cf[o] = v;
            else    Ch[o] = __float2half_rn(v);
        }
    }
}

// Merged Q+K+V projection: one launch, flat grid of 1088 tile-blocks.
// Blocks [0,1024): KV (even=K, odd=V, interleaved per (m,n) for A-row L2 reuse).
// Blocks [1024,1088): Q (64 tiles, fills the KV tail).
__global__ __launch_bounds__(256, 2) void qkv_kernel(
    const __half* __restrict__ Ahs, const __half* __restrict__ Akv,
    const __half* __restrict__ Wq, const __half* __restrict__ Wk,
    const __half* __restrict__ Wv,
    const float* __restrict__ bq, const float* __restrict__ bk,
    const float* __restrict__ bv,
    __half* __restrict__ Cq, __half* __restrict__ Ck, __half* __restrict__ Cv)
{
    extern __shared__ __half smh[];
    const int id = blockIdx.x;
    if (id < 1024) {
        const int isv  = id & 1;
        const int rest = id >> 1;                   // 0..511
        const int m0 = (rest >> 3) * 128;           // 64 m-blocks
        const int n0 = (rest & 7) * 128;            // 8 n-blocks
        if (isv) proj_tile(Akv, Wv, bv, Cv, nullptr, 1.0f, m0, n0, smh);
        else     proj_tile(Akv, Wk, bk, Ck, nullptr, 1.0f, m0, n0, smh);
    } else {
        const int q = id - 1024;                    // 0..63
        const int m0 = (q >> 3) * 128;
        const int n0 = (q & 7) * 128;
        proj_tile(Ahs, Wq, bq, Cq, nullptr, 0.125f, m0, n0, smh);
    }
}

// O projection (float final output)
__global__ __launch_bounds__(256, 2) void oproj_kernel(
    const __half* __restrict__ A, const __half* __restrict__ Bw,
    const float* __restrict__ bias, float* __restrict__ Cf)
{
    extern __shared__ __half smh[];
    proj_tile(A, Bw, bias, nullptr, Cf, 1.0f,
              blockIdx.y * 128, blockIdx.x * 128, smh);
}

// ---------------------------------------------------------------------------
// Fused flash attention v3 (R13-exact): raw mma.m16n8k16 + ldmatrix,
// register-resident P. 256 CTAs, 2 k-groups x 4 t-warps, 2 CTAs/SM.
// ---------------------------------------------------------------------------
static constexpr int HLD  = 72;
static constexpr int SLOTH = 2 * 64 * HLD;
static constexpr int OF_Q  = 4 * SLOTH;
static constexpr int HEND  = OF_Q + 64 * HLD;
static constexpr int OSLD  = 66;
static constexpr int FLASH_SMEM = HEND * 2 + (128 + 64 * OSLD) * 4;  // 100352 B

__global__ __launch_bounds__(256, 2) void flash_kernel()
{
    extern __shared__ __half smh[];
    const uint32_t sbase = smem_u32(smh);
    float* Lr  = (float*)(smh + HEND);
    float* Osm = Lr + 128;

    const int t0 = blockIdx.x * 64;
    const int z  = blockIdx.y;
    const int b  = z / H_;
    const int h  = z % H_;

    const int tid  = threadIdx.x;
    const int grp  = tid >> 7;
    const int gtid = tid & 127;
    const int w    = gtid >> 5;
    const int lane = tid & 31;
    const int qg   = lane >> 2;
    const int qt   = lane & 3;

    auto issue_kv = [&](int p) {
        const int c  = p >> 3;
        const int k0 = ((grp << 3) + (p & 7)) << 6;
        const int slot = (grp << 1) + (p & 1);
        const __half* Kb = h_K + ((size_t)(b * C_ + c) * K_ + k0) * E_ + h * 64;
        const __half* Vb = h_V + ((size_t)(b * C_ + c) * K_ + k0) * E_ + h * 64;
        const uint32_t sk = sbase + (uint32_t)(slot * SLOTH) * 2;
        const uint32_t sv = sk + (uint32_t)(64 * HLD) * 2;
        #pragma unroll
        for (int it = 0; it < 4; it++) {
            const int idx = gtid + it * 128;
            const int r = idx >> 3, q = (idx & 7) * 8;
            cp16(sk + (uint32_t)(r * HLD + q) * 2, Kb + (size_t)r * E_ + q);
            cp16(sv + (uint32_t)(r * HLD + q) * 2, Vb + (size_t)r * E_ + q);
        }
        CP_COMMIT();
    };

    {
        const __half* Qp = h_Q + (size_t)(b * T_ + t0) * E_ + h * 64;
        #pragma unroll
        for (int it = 0; it < 2; it++) {
            const int idx = tid + it * 256;
            const int r = idx >> 3, q = (idx & 7) * 8;
            cp16(sbase + (uint32_t)(OF_Q + r * HLD + q) * 2,
                 Qp + (size_t)r * E_ + q);
        }
        CP_COMMIT();
        issue_kv(0);
        CP_WAIT1();
        __syncthreads();
    }

    uint32_t Qf[4][4];
    {
        const int row = w * 16 + (lane & 15);
        const int dof = (lane >> 4) << 3;
        #pragma unroll
        for (int m = 0; m < 4; m++)
            ldsm_x4(Qf[m], sbase + (uint32_t)(OF_Q + row * HLD + m * 16 + dof) * 2);
    }

    float Oc[8][4];
    #pragma unroll
    for (int j = 0; j < 8; j++)
        #pragma unroll
        for (int r = 0; r < 4; r++) Oc[j][r] = 0.0f;
    float lc0 = 0.0f, lc1 = 0.0f;
    const int barid = grp + 1;

    const int krow_ = (lane & 7);
    const int kdof_ = (lane >> 3) << 3;
    const int vrow_ = (lane & 15);
    const int vdof_ = (lane >> 4) << 3;

    for (int p = 0; p < 32; p++) {
        CP_WAIT0();
        asm volatile("bar.sync %0, 128;" :: "r"(barid) : "memory");
        if (p + 1 < 32) issue_kv(p + 1);

        const int slot = (grp << 1) + (p & 1);
        const uint32_t skb = sbase + (uint32_t)(slot * SLOTH) * 2;
        const uint32_t svb = skb + (uint32_t)(64 * HLD) * 2;

        uint32_t Pr[8][2];
        #pragma unroll
        for (int j = 0; j < 8; j++) {
            float S[4] = {0.0f, 0.0f, 0.0f, 0.0f};
            const uint32_t ka = skb + (uint32_t)((j * 8 + krow_) * HLD + kdof_) * 2;
            #pragma unroll
            for (int m2 = 0; m2 < 2; m2++) {
                uint32_t kb[4];
                ldsm_x4(kb, ka + (uint32_t)(m2 * 32) * 2);
                mma16816(S, Qf[2 * m2][0], Qf[2 * m2][1], Qf[2 * m2][2], Qf[2 * m2][3],
                         kb[0], kb[1]);
                mma16816(S, Qf[2 * m2 + 1][0], Qf[2 * m2 + 1][1], Qf[2 * m2 + 1][2],
                         Qf[2 * m2 + 1][3], kb[2], kb[3]);
            }
            __half2 e01 = __floats2half2_rn(__expf(S[0]), __expf(S[1]));
            __half2 e23 = __floats2half2_rn(__expf(S[2]), __expf(S[3]));
            Pr[j][0] = *(uint32_t*)&e01;
            Pr[j][1] = *(uint32_t*)&e23;
            float2 f01 = __half22float2(e01);
            float2 f23 = __half22float2(e23);
            lc0 += f01.x + f01.y;
            lc1 += f23.x + f23.y;
        }

        #pragma unroll
        for (int m = 0; m < 4; m++) {
            const uint32_t va = svb + (uint32_t)((m * 16 + vrow_) * HLD + vdof_) * 2;
            #pragma unroll
            for (int j2 = 0; j2 < 4; j2++) {
                uint32_t vb[4];
                ldsm_x4t(vb, va + (uint32_t)(j2 * 16) * 2);
                mma16816(Oc[2 * j2], Pr[2 * m][0], Pr[2 * m][1],
                         Pr[2 * m + 1][0], Pr[2 * m + 1][1], vb[0], vb[1]);
                mma16816(Oc[2 * j2 + 1], Pr[2 * m][0], Pr[2 * m][1],
                         Pr[2 * m + 1][0], Pr[2 * m + 1][1], vb[2], vb[3]);
            }
        }

        if ((p & 7) == 7) {
            const int c = p >> 3;
            float r0 = lc0;
            r0 += __shfl_xor_sync(0xffffffffu, r0, 1);
            r0 += __shfl_xor_sync(0xffffffffu, r0, 2);
            float r1 = lc1;
            r1 += __shfl_xor_sync(0xffffffffu, r1, 1);
            r1 += __shfl_xor_sync(0xffffffffu, r1, 2);
            if (qt == 0) {
                Lr[grp * 64 + w * 16 + qg]     = r0;
                Lr[grp * 64 + w * 16 + qg + 8] = r1;
            }
            __syncthreads();
            const float li0 = 1.0f / ((float)C_ * (Lr[w * 16 + qg] + Lr[64 + w * 16 + qg]));
            const float li1 = 1.0f / ((float)C_ * (Lr[w * 16 + qg + 8] + Lr[64 + w * 16 + qg + 8]));
            if (grp == 0) {
                #pragma unroll
                for (int j = 0; j < 8; j++) {
                    float* o0 = Osm + (w * 16 + qg) * OSLD + j * 8 + 2 * qt;
                    float* o1 = o0 + 8 * OSLD;
                    if (c == 0) {
                        o0[0] = Oc[j][0] * li0; o0[1] = Oc[j][1] * li0;
                        o1[0] = Oc[j][2] * li1; o1[1] = Oc[j][3] * li1;
                    } else {
                        o0[0] += Oc[j][0] * li0; o0[1] += Oc[j][1] * li0;
                        o1[0] += Oc[j][2] * li1; o1[1] += Oc[j][3] * li1;
                    }
                }
            }
            __syncthreads();
            if (grp == 1) {
                #pragma unroll
                for (int j = 0; j < 8; j++) {
                    float* o0 = Osm + (w * 16 + qg) * OSLD + j * 8 + 2 * qt;
                    float* o1 = o0 + 8 * OSLD;
                    o0[0] += Oc[j][0] * li0; o0[1] += Oc[j][1] * li0;
                    o1[0] += Oc[j][2] * li1; o1[1] += Oc[j][3] * li1;
                }
            }
            __syncthreads();
            #pragma unroll
            for (int j = 0; j < 8; j++)
                #pragma unroll
                for (int r = 0; r < 4; r++) Oc[j][r] = 0.0f;
            lc0 = lc1 = 0.0f;
        }
    }

    {
        __half* Ap = h_attn + (size_t)(b * T_ + t0) * E_ + h * 64;
        for (int e = tid; e < 64 * 64; e += 256) {
            const int r = e >> 6, d = e & 63;
            Ap[(size_t)r * E_ + d] = __float2half_rn(Osm[r * OSLD + d]);
        }
    }
}

// ---------------------------------------------------------------------------
// Launch
// ---------------------------------------------------------------------------
extern "C" void kernel_launch(void* const* d_in, const int* in_sizes, int n_in,
                              void* d_out, int out_size)
{
    const float* HS  = (const float*)d_in[0];
    const float* KVS = (const float*)d_in[1];
    const float* Wq  = (const float*)d_in[2];
    const float* bq  = (const float*)d_in[3];
    const float* Wk  = (const float*)d_in[4];
    const float* bk  = (const float*)d_in[5];
    const float* Wv  = (const float*)d_in[6];
    const float* bv  = (const float*)d_in[7];
    const float* Wo  = (const float*)d_in[8];
    const float* bo  = (const float*)d_in[9];
    float* out = (float*)d_out;

    cudaFuncSetAttribute(qkv_kernel,   cudaFuncAttributeMaxDynamicSharedMemorySize, SMEM_PROJ);
    cudaFuncSetAttribute(oproj_kernel, cudaFuncAttributeMaxDynamicSharedMemorySize, SMEM_PROJ);
    cudaFuncSetAttribute(flash_kernel, cudaFuncAttributeMaxDynamicSharedMemorySize, FLASH_SMEM);

    __half *pHS, *pKV, *pWq, *pWk, *pWv, *pWo, *pQ, *pK, *pV, *pA;
    cudaGetSymbolAddress((void**)&pHS, h_HS);
    cudaGetSymbolAddress((void**)&pKV, h_KV);
    cudaGetSymbolAddress((void**)&pWq, h_Wq);
    cudaGetSymbolAddress((void**)&pWk, h_Wk);
    cudaGetSymbolAddress((void**)&pWv, h_Wv);
    cudaGetSymbolAddress((void**)&pWo, h_Wo);
    cudaGetSymbolAddress((void**)&pQ,  h_Q);
    cudaGetSymbolAddress((void**)&pK,  h_K);
    cudaGetSymbolAddress((void**)&pV,  h_V);
    cudaGetSymbolAddress((void**)&pA,  h_attn);

    // 0) Convert all GEMM operands to fp16 (RN) — single launch
    f2h_all<<<(N4_TOTAL + 255) / 256, 256>>>(
        (const float4*)HS, (const float4*)KVS,
        (const float4*)Wq, (const float4*)Wk, (const float4*)Wv, (const float4*)Wo,
        (uint2*)pHS, (uint2*)pKV, (uint2*)pWq, (uint2*)pWk, (uint2*)pWv, (uint2*)pWo);

    // 1) Q + K + V projections, single launch (1088 tile-blocks)
    qkv_kernel<<<1088, 256, SMEM_PROJ>>>(
        pHS, pKV, pWq, pWk, pWv, bq, bk, bv, pQ, pK, pV);

    // 2) Fused attention (scores + softmax + PV + channel pooling)
    flash_kernel<<<dim3(T_ / 64, B_ * H_), 256, FLASH_SMEM>>>();

    // 3) Output projection (float final output)
    oproj_kernel<<<dim3(E_ / 128, (B_ * T_) / 128), 256, SMEM_PROJ>>>(
        pA, pWo, bo, out);
}

// round 16
// speedup vs baseline: 1.4040x; 1.0330x over previous
#include <cuda_runtime.h>
#include <mma.h>
#include <cuda_fp16.h>
#include <cstdint>

using namespace nvcuda;

// Problem constants
static constexpr int B_ = 2;
static constexpr int C_ = 4;
static constexpr int T_ = 512;
static constexpr int K_ = 1024;
static constexpr int E_ = 1024;
static constexpr int H_ = 16;
static constexpr int D_ = 64;

// Scratch (device globals, allocation-free). All GEMM operands in fp16.
__device__ __half h_HS[B_ * T_ * E_];
__device__ __half h_KV[B_ * C_ * K_ * E_];
__device__ __half h_Wq[E_ * E_];
__device__ __half h_Wk[E_ * E_];
__device__ __half h_Wv[E_ * E_];
__device__ __half h_Wo[E_ * E_];
__device__ __half h_Q[B_ * T_ * E_];
__device__ __half h_K[B_ * C_ * K_ * E_];
__device__ __half h_V[B_ * C_ * K_ * E_];
__device__ __half h_attn[B_ * T_ * E_];

// ---------------------------------------------------------------------------
// Helpers
// ---------------------------------------------------------------------------
__device__ __forceinline__ uint32_t smem_u32(const void* p) {
    uint32_t a;
    asm("{ .reg .u64 t; cvta.to.shared.u64 t, %1; cvt.u32.u64 %0, t; }"
        : "=r"(a) : "l"(p));
    return a;
}

__device__ __forceinline__ void cp16(uint32_t saddr, const void* g) {
    asm volatile("cp.async.cg.shared.global [%0], [%1], 16;"
                 :: "r"(saddr), "l"(g) : "memory");
}
#define CP_COMMIT() asm volatile("cp.async.commit_group;" ::: "memory")
#define CP_WAIT0()  asm volatile("cp.async.wait_group 0;" ::: "memory")
#define CP_WAIT1()  asm volatile("cp.async.wait_group 1;" ::: "memory")

__device__ __forceinline__ void ldsm_x4(uint32_t (&r)[4], uint32_t a) {
    asm volatile("ldmatrix.sync.aligned.m8n8.x4.shared.b16 {%0,%1,%2,%3}, [%4];"
                 : "=r"(r[0]), "=r"(r[1]), "=r"(r[2]), "=r"(r[3]) : "r"(a));
}
__device__ __forceinline__ void ldsm_x4t(uint32_t (&r)[4], uint32_t a) {
    asm volatile("ldmatrix.sync.aligned.m8n8.x4.trans.shared.b16 {%0,%1,%2,%3}, [%4];"
                 : "=r"(r[0]), "=r"(r[1]), "=r"(r[2]), "=r"(r[3]) : "r"(a));
}
__device__ __forceinline__ void mma16816(float (&c)[4],
                                         uint32_t a0, uint32_t a1, uint32_t a2, uint32_t a3,
                                         uint32_t b0, uint32_t b1) {
    asm volatile(
        "mma.sync.aligned.m16n8k16.row.col.f32.f16.f16.f32 "
        "{%0,%1,%2,%3},{%4,%5,%6,%7},{%8,%9},{%0,%1,%2,%3};"
        : "+f"(c[0]), "+f"(c[1]), "+f"(c[2]), "+f"(c[3])
        : "r"(a0), "r"(a1), "r"(a2), "r"(a3), "r"(b0), "r"(b1));
}

// ---------------------------------------------------------------------------
// Fused float -> fp16 (RN) conversion for all six operand tensors, one launch.
// ---------------------------------------------------------------------------
static constexpr int N4_HS = (B_ * T_ * E_) / 4;
static constexpr int N4_KV = (B_ * C_ * K_ * E_) / 4;
static constexpr int N4_W  = (E_ * E_) / 4;
static constexpr int N4_TOTAL = N4_HS + N4_KV + 4 * N4_W;

__global__ void f2h_all(const float4* __restrict__ hs,
                        const float4* __restrict__ kvs,
                        const float4* __restrict__ wq, const float4* __restrict__ wk,
                        const float4* __restrict__ wv, const float4* __restrict__ wo,
                        uint2* __restrict__ ohs, uint2* __restrict__ okv,
                        uint2* __restrict__ owq, uint2* __restrict__ owk,
                        uint2* __restrict__ owv, uint2* __restrict__ owo)
{
    int i = blockIdx.x * 256 + threadIdx.x;
    if (i >= N4_TOTAL) return;
    const float4* src;
    uint2* dst;
    int j = i;
    if (j < N4_HS)                 { src = hs;  dst = ohs; }
    else if ((j -= N4_HS) < N4_KV) { src = kvs; dst = okv; }
    else if ((j -= N4_KV) < N4_W)  { src = wq;  dst = owq; }
    else if ((j -= N4_W) < N4_W)   { src = wk;  dst = owk; }
    else if ((j -= N4_W) < N4_W)   { src = wv;  dst = owv; }
    else { j -= N4_W;                src = wo;  dst = owo; }
    float4 v = src[j];
    __half2 a = __floats2half2_rn(v.x, v.y);
    __half2 b = __floats2half2_rn(v.z, v.w);
    dst[j] = make_uint2(*(uint32_t*)&a, *(uint32_t*)&b);
}

// ---------------------------------------------------------------------------
// fp16 wmma projection GEMM tile body, templated on A-tile rows (MR).
//   MR=128: 4m x 2n warp grid, 32x64 warp tile  (qkv — R10/R13-proven config)
//   MR=64 : 2m x 4n warp grid, 32x32 warp tile  (oproj — more CTAs, less/CTA)
// BK=64, stride 72 halves, 3-stage cp.async, 256 threads.
// Per-element reduction order is identical for both MR (same BK sequence,
// same fragment k-order) -> numerics bit-identical to R13/R14.
// ---------------------------------------------------------------------------
static constexpr int SLDH = 72;
static constexpr int SMEM_PROJ  = 3 * (128 + 128) * SLDH * 2;  // 110592 B
static constexpr int SMEM_OPROJ = 3 * (64 + 128) * SLDH * 2;   //  82944 B

template <int MR>
__device__ __forceinline__ void proj_tile(
    const __half* __restrict__ A,
    const __half* __restrict__ Bw,
    const float* __restrict__ bias,
    __half* __restrict__ Ch, float* __restrict__ Cf,
    float scale, int m0, int n0, __half* smh)
{
    constexpr int ROWS = MR + 128;        // A rows + B rows per stage
    constexpr int WNC  = (MR == 128) ? 64 : 32;   // warp n-cols
    constexpr int NBF  = WNC / 16;                // B frags per warp
    constexpr int NA_IT = (MR * 8) / 256;         // A cp iterations

    const uint32_t sbase = smem_u32(smh);

    const int tid  = threadIdx.x;
    const int w    = tid >> 5;
    const int lane = tid & 31;
    const int wm   = (MR == 128) ? (w >> 1) : (w >> 2);
    const int wn   = (MR == 128) ? (w & 1) : (w & 3);

    auto issue = [&](int kt, int s) {
        const int ko = kt * 64;
        const uint32_t sA = sbase + (uint32_t)(s * ROWS * SLDH) * 2;
        const uint32_t sB = sA + (uint32_t)(MR * SLDH) * 2;
        #pragma unroll
        for (int it = 0; it < NA_IT; it++) {
            const int idx = tid + it * 256;
            const int r = idx >> 3, q = (idx & 7) * 8;
            cp16(sA + (uint32_t)(r * SLDH + q) * 2,
                 A + (size_t)(m0 + r) * E_ + ko + q);
        }
        #pragma unroll
        for (int it = 0; it < 4; it++) {
            const int idx = tid + it * 256;
            const int r = idx >> 3, q = (idx & 7) * 8;
            cp16(sB + (uint32_t)(r * SLDH + q) * 2,
                 Bw + (size_t)(n0 + r) * E_ + ko + q);
        }
        CP_COMMIT();
    };

    wmma::fragment<wmma::accumulator, 16, 16, 16, float> acc[2][NBF];
    #pragma unroll
    for (int i = 0; i < 2; i++)
        #pragma unroll
        for (int j = 0; j < NBF; j++)
            wmma::fill_fragment(acc[i][j], 0.0f);

    constexpr int nk = E_ / 64;
    issue(0, 0);
    issue(1, 1);

    for (int kt = 0; kt < nk; kt++) {
        if (kt == nk - 1) { CP_WAIT0(); } else { CP_WAIT1(); }
        __syncthreads();
        if (kt + 2 < nk) issue(kt + 2, (kt + 2) % 3);

        const int s = kt % 3;
        const __half* As_ = smh + s * ROWS * SLDH + wm * 32 * SLDH;
        const __half* Bs_ = smh + s * ROWS * SLDH + MR * SLDH + wn * WNC * SLDH;

        #pragma unroll
        for (int ks = 0; ks < 4; ks++) {
            wmma::fragment<wmma::matrix_a, 16, 16, 16, __half,
                           wmma::row_major> af[2];
            wmma::fragment<wmma::matrix_b, 16, 16, 16, __half,
                           wmma::col_major> bf[NBF];
            #pragma unroll
            for (int i = 0; i < 2; i++)
                wmma::load_matrix_sync(af[i], As_ + i * 16 * SLDH + ks * 16, SLDH);
            #pragma unroll
            for (int j = 0; j < NBF; j++)
                wmma::load_matrix_sync(bf[j], Bs_ + j * 16 * SLDH + ks * 16, SLDH);
            #pragma unroll
            for (int i = 0; i < 2; i++)
                #pragma unroll
                for (int j = 0; j < NBF; j++)
                    wmma::mma_sync(acc[i][j], af[i], bf[j], acc[i][j]);
        }
    }

    // Epilogue: per-warp float staging in smem, coalesced write.
    __syncthreads();
    float* stg = (float*)smh + w * 32 * 68;
    #pragma unroll
    for (int i = 0; i < 2; i++)
        #pragma unroll
        for (int j = 0; j < NBF; j++)
            wmma::store_matrix_sync(stg + i * 16 * 68 + j * 16, acc[i][j],
                                    68, wmma::mem_row_major);
    __syncwarp();

    const int rowbase = m0 + wm * 32;
    const int colbase = n0 + wn * WNC;
    for (int r = 0; r < 32; r++) {
        #pragma unroll
        for (int cb = 0; cb < WNC; cb += 32) {
            const int c = cb + lane;
            const int col = colbase + c;
            const float v = (stg[r * 68 + c] + bias[col]) * scale;
            const size_t o = (size_t)(rowbase + r) * E_ + col;
            if (Cf) Cf[o] = v;
            else    Ch[o] = __float2half_rn(v);
        }
    }
}

// Merged Q+K+V projection: one launch, flat grid of 1088 tile-blocks.
// Blocks [0,1024): KV (even=K, odd=V, interleaved per (m,n) for A-row L2 reuse).
// Blocks [1024,1088): Q (64 tiles, fills the KV tail).
__global__ __launch_bounds__(256, 2) void qkv_kernel(
    const __half* __restrict__ Ahs, const __half* __restrict__ Akv,
    const __half* __restrict__ Wq, const __half* __restrict__ Wk,
    const __half* __restrict__ Wv,
    const float* __restrict__ bq, const float* __restrict__ bk,
    const float* __restrict__ bv,
    __half* __restrict__ Cq, __half* __restrict__ Ck, __half* __restrict__ Cv)
{
    extern __shared__ __half smh[];
    const int id = blockIdx.x;
    if (id < 1024) {
        const int isv  = id & 1;
        const int rest = id >> 1;                   // 0..511
        const int m0 = (rest >> 3) * 128;           // 64 m-blocks
        const int n0 = (rest & 7) * 128;            // 8 n-blocks
        if (isv) proj_tile<128>(Akv, Wv, bv, Cv, nullptr, 1.0f, m0, n0, smh);
        else     proj_tile<128>(Akv, Wk, bk, Ck, nullptr, 1.0f, m0, n0, smh);
    } else {
        const int q = id - 1024;                    // 0..63
        const int m0 = (q >> 3) * 128;
        const int n0 = (q & 7) * 128;
        proj_tile<128>(Ahs, Wq, bq, Cq, nullptr, 0.125f, m0, n0, smh);
    }
}

// O projection (float final output): 64x128 tiles -> 128 CTAs (2x coverage
// of the chip vs 64; latency-bound kernel so more CTAs = direct speedup).
__global__ __launch_bounds__(256, 2) void oproj_kernel(
    const __half* __restrict__ A, const __half* __restrict__ Bw,
    const float* __restrict__ bias, float* __restrict__ Cf)
{
    extern __shared__ __half smh[];
    proj_tile<64>(A, Bw, bias, nullptr, Cf, 1.0f,
                  blockIdx.y * 64, blockIdx.x * 128, smh);
}

// ---------------------------------------------------------------------------
// Fused flash attention v3 (R13-exact): raw mma.m16n8k16 + ldmatrix,
// register-resident P. 256 CTAs, 2 k-groups x 4 t-warps, 2 CTAs/SM.
// ---------------------------------------------------------------------------
static constexpr int HLD  = 72;
static constexpr int SLOTH = 2 * 64 * HLD;
static constexpr int OF_Q  = 4 * SLOTH;
static constexpr int HEND  = OF_Q + 64 * HLD;
static constexpr int OSLD  = 66;
static constexpr int FLASH_SMEM = HEND * 2 + (128 + 64 * OSLD) * 4;  // 100352 B

__global__ __launch_bounds__(256, 2) void flash_kernel()
{
    extern __shared__ __half smh[];
    const uint32_t sbase = smem_u32(smh);
    float* Lr  = (float*)(smh + HEND);
    float* Osm = Lr + 128;

    const int t0 = blockIdx.x * 64;
    const int z  = blockIdx.y;
    const int b  = z / H_;
    const int h  = z % H_;

    const int tid  = threadIdx.x;
    const int grp  = tid >> 7;
    const int gtid = tid & 127;
    const int w    = gtid >> 5;
    const int lane = tid & 31;
    const int qg   = lane >> 2;
    const int qt   = lane & 3;

    auto issue_kv = [&](int p) {
        const int c  = p >> 3;
        const int k0 = ((grp << 3) + (p & 7)) << 6;
        const int slot = (grp << 1) + (p & 1);
        const __half* Kb = h_K + ((size_t)(b * C_ + c) * K_ + k0) * E_ + h * 64;
        const __half* Vb = h_V + ((size_t)(b * C_ + c) * K_ + k0) * E_ + h * 64;
        const uint32_t sk = sbase + (uint32_t)(slot * SLOTH) * 2;
        const uint32_t sv = sk + (uint32_t)(64 * HLD) * 2;
        #pragma unroll
        for (int it = 0; it < 4; it++) {
            const int idx = gtid + it * 128;
            const int r = idx >> 3, q = (idx & 7) * 8;
            cp16(sk + (uint32_t)(r * HLD + q) * 2, Kb + (size_t)r * E_ + q);
            cp16(sv + (uint32_t)(r * HLD + q) * 2, Vb + (size_t)r * E_ + q);
        }
        CP_COMMIT();
    };

    {
        const __half* Qp = h_Q + (size_t)(b * T_ + t0) * E_ + h * 64;
        #pragma unroll
        for (int it = 0; it < 2; it++) {
            const int idx = tid + it * 256;
            const int r = idx >> 3, q = (idx & 7) * 8;
            cp16(sbase + (uint32_t)(OF_Q + r * HLD + q) * 2,
                 Qp + (size_t)r * E_ + q);
        }
        CP_COMMIT();
        issue_kv(0);
        CP_WAIT1();
        __syncthreads();
    }

    uint32_t Qf[4][4];
    {
        const int row = w * 16 + (lane & 15);
        const int dof = (lane >> 4) << 3;
        #pragma unroll
        for (int m = 0; m < 4; m++)
            ldsm_x4(Qf[m], sbase + (uint32_t)(OF_Q + row * HLD + m * 16 + dof) * 2);
    }

    float Oc[8][4];
    #pragma unroll
    for (int j = 0; j < 8; j++)
        #pragma unroll
        for (int r = 0; r < 4; r++) Oc[j][r] = 0.0f;
    float lc0 = 0.0f, lc1 = 0.0f;
    const int barid = grp + 1;

    const int krow_ = (lane & 7);
    const int kdof_ = (lane >> 3) << 3;
    const int vrow_ = (lane & 15);
    const int vdof_ = (lane >> 4) << 3;

    for (int p = 0; p < 32; p++) {
        CP_WAIT0();
        asm volatile("bar.sync %0, 128;" :: "r"(barid) : "memory");
        if (p + 1 < 32) issue_kv(p + 1);

        const int slot = (grp << 1) + (p & 1);
        const uint32_t skb = sbase + (uint32_t)(slot * SLOTH) * 2;
        const uint32_t svb = skb + (uint32_t)(64 * HLD) * 2;

        uint32_t Pr[8][2];
        #pragma unroll
        for (int j = 0; j < 8; j++) {
            float S[4] = {0.0f, 0.0f, 0.0f, 0.0f};
            const uint32_t ka = skb + (uint32_t)((j * 8 + krow_) * HLD + kdof_) * 2;
            #pragma unroll
            for (int m2 = 0; m2 < 2; m2++) {
                uint32_t kb[4];
                ldsm_x4(kb, ka + (uint32_t)(m2 * 32) * 2);
                mma16816(S, Qf[2 * m2][0], Qf[2 * m2][1], Qf[2 * m2][2], Qf[2 * m2][3],
                         kb[0], kb[1]);
                mma16816(S, Qf[2 * m2 + 1][0], Qf[2 * m2 + 1][1], Qf[2 * m2 + 1][2],
                         Qf[2 * m2 + 1][3], kb[2], kb[3]);
            }
            __half2 e01 = __floats2half2_rn(__expf(S[0]), __expf(S[1]));
            __half2 e23 = __floats2half2_rn(__expf(S[2]), __expf(S[3]));
            Pr[j][0] = *(uint32_t*)&e01;
            Pr[j][1] = *(uint32_t*)&e23;
            float2 f01 = __half22float2(e01);
            float2 f23 = __half22float2(e23);
            lc0 += f01.x + f01.y;
            lc1 += f23.x + f23.y;
        }

        #pragma unroll
        for (int m = 0; m < 4; m++) {
            const uint32_t va = svb + (uint32_t)((m * 16 + vrow_) * HLD + vdof_) * 2;
            #pragma unroll
            for (int j2 = 0; j2 < 4; j2++) {
                uint32_t vb[4];
                ldsm_x4t(vb, va + (uint32_t)(j2 * 16) * 2);
                mma16816(Oc[2 * j2], Pr[2 * m][0], Pr[2 * m][1],
                         Pr[2 * m + 1][0], Pr[2 * m + 1][1], vb[0], vb[1]);
                mma16816(Oc[2 * j2 + 1], Pr[2 * m][0], Pr[2 * m][1],
                         Pr[2 * m + 1][0], Pr[2 * m + 1][1], vb[2], vb[3]);
            }
        }

        if ((p & 7) == 7) {
            const int c = p >> 3;
            float r0 = lc0;
            r0 += __shfl_xor_sync(0xffffffffu, r0, 1);
            r0 += __shfl_xor_sync(0xffffffffu, r0, 2);
            float r1 = lc1;
            r1 += __shfl_xor_sync(0xffffffffu, r1, 1);
            r1 += __shfl_xor_sync(0xffffffffu, r1, 2);
            if (qt == 0) {
                Lr[grp * 64 + w * 16 + qg]     = r0;
                Lr[grp * 64 + w * 16 + qg + 8] = r1;
            }
            __syncthreads();
            const float li0 = 1.0f / ((float)C_ * (Lr[w * 16 + qg] + Lr[64 + w * 16 + qg]));
            const float li1 = 1.0f / ((float)C_ * (Lr[w * 16 + qg + 8] + Lr[64 + w * 16 + qg + 8]));
            if (grp == 0) {
                #pragma unroll
                for (int j = 0; j < 8; j++) {
                    float* o0 = Osm + (w * 16 + qg) * OSLD + j * 8 + 2 * qt;
                    float* o1 = o0 + 8 * OSLD;
                    if (c == 0) {
                        o0[0] = Oc[j][0] * li0; o0[1] = Oc[j][1] * li0;
                        o1[0] = Oc[j][2] * li1; o1[1] = Oc[j][3] * li1;
                    } else {
                        o0[0] += Oc[j][0] * li0; o0[1] += Oc[j][1] * li0;
                        o1[0] += Oc[j][2] * li1; o1[1] += Oc[j][3] * li1;
                    }
                }
            }
            __syncthreads();
            if (grp == 1) {
                #pragma unroll
                for (int j = 0; j < 8; j++) {
                    float* o0 = Osm + (w * 16 + qg) * OSLD + j * 8 + 2 * qt;
                    float* o1 = o0 + 8 * OSLD;
                    o0[0] += Oc[j][0] * li0; o0[1] += Oc[j][1] * li0;
                    o1[0] += Oc[j][2] * li1; o1[1] += Oc[j][3] * li1;
                }
            }
            __syncthreads();
            #pragma unroll
            for (int j = 0; j < 8; j++)
                #pragma unroll
                for (int r = 0; r < 4; r++) Oc[j][r] = 0.0f;
            lc0 = lc1 = 0.0f;
        }
    }

    {
        __half* Ap = h_attn + (size_t)(b * T_ + t0) * E_ + h * 64;
        for (int e = tid; e < 64 * 64; e += 256) {
            const int r = e >> 6, d = e & 63;
            Ap[(size_t)r * E_ + d] = __float2half_rn(Osm[r * OSLD + d]);
        }
    }
}

// ---------------------------------------------------------------------------
// Launch
// ---------------------------------------------------------------------------
extern "C" void kernel_launch(void* const* d_in, const int* in_sizes, int n_in,
                              void* d_out, int out_size)
{
    const float* HS  = (const float*)d_in[0];
    const float* KVS = (const float*)d_in[1];
    const float* Wq  = (const float*)d_in[2];
    const float* bq  = (const float*)d_in[3];
    const float* Wk  = (const float*)d_in[4];
    const float* bk  = (const float*)d_in[5];
    const float* Wv  = (const float*)d_in[6];
    const float* bv  = (const float*)d_in[7];
    const float* Wo  = (const float*)d_in[8];
    const float* bo  = (const float*)d_in[9];
    float* out = (float*)d_out;

    cudaFuncSetAttribute(qkv_kernel,   cudaFuncAttributeMaxDynamicSharedMemorySize, SMEM_PROJ);
    cudaFuncSetAttribute(oproj_kernel, cudaFuncAttributeMaxDynamicSharedMemorySize, SMEM_OPROJ);
    cudaFuncSetAttribute(flash_kernel, cudaFuncAttributeMaxDynamicSharedMemorySize, FLASH_SMEM);

    __half *pHS, *pKV, *pWq, *pWk, *pWv, *pWo, *pQ, *pK, *pV, *pA;
    cudaGetSymbolAddress((void**)&pHS, h_HS);
    cudaGetSymbolAddress((void**)&pKV, h_KV);
    cudaGetSymbolAddress((void**)&pWq, h_Wq);
    cudaGetSymbolAddress((void**)&pWk, h_Wk);
    cudaGetSymbolAddress((void**)&pWv, h_Wv);
    cudaGetSymbolAddress((void**)&pWo, h_Wo);
    cudaGetSymbolAddress((void**)&pQ,  h_Q);
    cudaGetSymbolAddress((void**)&pK,  h_K);
    cudaGetSymbolAddress((void**)&pV,  h_V);
    cudaGetSymbolAddress((void**)&pA,  h_attn);

    // 0) Convert all GEMM operands to fp16 (RN) — single launch
    f2h_all<<<(N4_TOTAL + 255) / 256, 256>>>(
        (const float4*)HS, (const float4*)KVS,
        (const float4*)Wq, (const float4*)Wk, (const float4*)Wv, (const float4*)Wo,
        (uint2*)pHS, (uint2*)pKV, (uint2*)pWq, (uint2*)pWk, (uint2*)pWv, (uint2*)pWo);

    // 1) Q + K + V projections, single launch (1088 tile-blocks)
    qkv_kernel<<<1088, 256, SMEM_PROJ>>>(
        pHS, pKV, pWq, pWk, pWv, bq, bk, bv, pQ, pK, pV);

    // 2) Fused attention (scores + softmax + PV + channel pooling)
    flash_kernel<<<dim3(T_ / 64, B_ * H_), 256, FLASH_SMEM>>>();

    // 3) Output projection: 64x128 tiles, 128 CTAs (float final output)
    oproj_kernel<<<dim3(E_ / 128, (B_ * T_) / 64), 256, SMEM_OPROJ>>>(
        pA, pWo, bo, out);
}